// round 2
// baseline (speedup 1.0000x reference)
#include <cuda_runtime.h>
#include <cuda_bf16.h>
#include <math.h>

// ---------------- problem constants ----------------
#define BB   128
#define TT   64
#define NIMG (BB*TT)          // 8192
#define HI   50
#define WI   60
#define HO   25
#define WO   30
#define EMB  750
#define QS   100
#define HSZ  400
#define NCLS 10

// ---------------- f32x2 packed helpers ----------------
typedef unsigned long long f32x2;

__device__ __forceinline__ f32x2 pk2(float x, float y) {
    f32x2 r; asm("mov.b64 %0, {%1, %2};" : "=l"(r) : "f"(x), "f"(y)); return r;
}
__device__ __forceinline__ void unpk2(f32x2 v, float &x, float &y) {
    asm("mov.b64 {%0, %1}, %2;" : "=f"(x), "=f"(y) : "l"(v));
}
__device__ __forceinline__ void fma2(f32x2 &d, f32x2 a, f32x2 b) {
    asm("fma.rn.f32x2 %0, %1, %2, %0;" : "+l"(d) : "l"(a), "l"(b));
}
__device__ __forceinline__ f32x2 add2(f32x2 a, f32x2 b) {
    f32x2 d; asm("add.rn.f32x2 %0, %1, %2;" : "=l"(d) : "l"(a), "l"(b)); return d;
}
__device__ __forceinline__ float lky(float x) { return fmaxf(x, 0.01f * x); }

// ---------------- scratch (static device memory; allowed) ----------------
__device__ float g_emb[NIMG * EMB];      // 24.6 MB
__device__ float g_E[NIMG * QS];         //  3.3 MB  (emb @ Qw[:750] + Qb)
__device__ float g_Hall[NIMG * HSZ];     // 13.1 MB
__device__ float g_OutAll[NIMG * QS];    //  3.3 MB

// =====================================================================
// Kernel A v2: fused conv1(1->16,3x3,s1,p1)+leaky -> conv2(16->1,3x3,s2,p1)+leaky
// One CTA per image.
//  - zero-padded SMEM image  -> no bounds predicates, vector row loads
//  - 4 conv1 rows + 2 conv2 rows per iteration -> 2 syncs / 13 iters
//  - conv2 16-channel reduction via warp shuffles (cp = low 3 lane bits)
// =====================================================================
__global__ void __launch_bounds__(256) conv_embed_kernel(
    const float *__restrict__ In,
    const float *__restrict__ w1, const float *__restrict__ b1,
    const float *__restrict__ w2, const float *__restrict__ b2,
    float *__restrict__ emb_out)
{
    __shared__ __align__(16) float pimg[52 * 64];   // [(r+1)][(x+1)], stride 64
    __shared__ f32x2 rb[6][61][8];                  // [row%6][x+1][cpair], col 0 = zero pad
    __shared__ f32x2 sw1[9][8];
    __shared__ f32x2 sw2[9][8];
    __shared__ f32x2 sb1[8];
    __shared__ float emb_s[EMB];

    const int tid = threadIdx.x;
    const float *imgg = In + (size_t)blockIdx.x * (HI * WI);

    // padded image load (predicates only here, once)
    for (int i = tid; i < 52 * 64; i += 256) {
        int pr = i >> 6, pc = i & 63;
        int r = pr - 1, x = pc - 1;
        pimg[i] = (r >= 0 && r < HI && x >= 0 && x < WI) ? imgg[r * WI + x] : 0.f;
    }
    if (tid < 72) {
        int tap = tid / 8, cp = tid % 8;
        sw1[tap][cp] = pk2(w1[(2 * cp) * 9 + tap], w1[(2 * cp + 1) * 9 + tap]);
        sw2[tap][cp] = pk2(w2[(2 * cp) * 9 + tap], w2[(2 * cp + 1) * 9 + tap]);
    }
    if (tid < 8) sb1[tid] = pk2(b1[2 * tid], b1[2 * tid + 1]);
    // zero whole ring buffer once (covers row -1 slot and x=0 pad column)
    for (int i = tid; i < 6 * 61 * 8; i += 256) ((f32x2 *)rb)[i] = 0ull;
    const float bias2 = b2[0];
    __syncthreads();

    for (int ii = 0; ii < 13; ii++) {
        const int r0 = 4 * ii;
        const int nrows = (ii < 12) ? 4 : 2;           // conv1 rows this iter
        const int n2rows = nrows >> 1;                 // conv2 rows this iter

        // ---- conv1: rows r0 .. r0+nrows-1 ----
        {
            const int total = nrows * 15 * 8;
            for (int task = tid; task < total; task += 256) {
                int cp = task & 7;
                int rest = task >> 3;
                int xg = rest % 15;
                int rowsel = rest / 15;
                int r = r0 + rowsel;
                int xb = 4 * xg;
                f32x2 a0 = sb1[cp], a1 = a0, a2 = a0, a3 = a0;
                #pragma unroll
                for (int dy = 0; dy < 3; dy++) {
                    const float *row = &pimg[(r + dy) * 64 + xb];
                    float4 v4 = *(const float4 *)row;
                    float2 v2 = *(const float2 *)(row + 4);
                    f32x2 cc0 = pk2(v4.x, v4.x), cc1 = pk2(v4.y, v4.y);
                    f32x2 cc2 = pk2(v4.z, v4.z), cc3 = pk2(v4.w, v4.w);
                    f32x2 cc4 = pk2(v2.x, v2.x), cc5 = pk2(v2.y, v2.y);
                    f32x2 wa = sw1[dy * 3 + 0][cp];
                    f32x2 wb = sw1[dy * 3 + 1][cp];
                    f32x2 wc = sw1[dy * 3 + 2][cp];
                    fma2(a0, cc0, wa); fma2(a0, cc1, wb); fma2(a0, cc2, wc);
                    fma2(a1, cc1, wa); fma2(a1, cc2, wb); fma2(a1, cc3, wc);
                    fma2(a2, cc2, wa); fma2(a2, cc3, wb); fma2(a2, cc4, wc);
                    fma2(a3, cc3, wa); fma2(a3, cc4, wb); fma2(a3, cc5, wc);
                }
                int rs = r % 6;
                float lo, hi;
                unpk2(a0, lo, hi); rb[rs][xb + 1][cp] = pk2(lky(lo), lky(hi));
                unpk2(a1, lo, hi); rb[rs][xb + 2][cp] = pk2(lky(lo), lky(hi));
                unpk2(a2, lo, hi); rb[rs][xb + 3][cp] = pk2(lky(lo), lky(hi));
                unpk2(a3, lo, hi); rb[rs][xb + 4][cp] = pk2(lky(lo), lky(hi));
            }
        }
        __syncthreads();

        // ---- conv2: rows 2*ii .. 2*ii+n2rows-1, shuffle-reduced over cp ----
        {
            const int total2 = n2rows * 30 * 8;
            for (int base = 0; base < total2; base += 256) {
                int task = base + tid;
                bool valid = (task < total2);
                int tt = valid ? task : 0;
                int cp = tt & 7;
                int rest = tt >> 3;
                int x2 = rest % 30;
                int rsel = rest / 30;
                int i2 = 2 * ii + rsel;
                f32x2 acc = 0ull;
                #pragma unroll
                for (int dy = 0; dy < 3; dy++) {
                    int rr = (2 * i2 + dy + 5) % 6;   // row (2*i2+dy-1) mod 6
                    #pragma unroll
                    for (int dx = 0; dx < 3; dx++) {
                        fma2(acc, rb[rr][2 * x2 + dx][cp], sw2[dy * 3 + dx][cp]);
                    }
                }
                float lo, hi; unpk2(acc, lo, hi);
                float s = lo + hi;
                s += __shfl_xor_sync(0xffffffffu, s, 1);
                s += __shfl_xor_sync(0xffffffffu, s, 2);
                s += __shfl_xor_sync(0xffffffffu, s, 4);
                if (valid && cp == 0) emb_s[i2 * 30 + x2] = lky(s + bias2);
            }
        }
        __syncthreads();
    }

    float *eo = emb_out + (size_t)blockIdx.x * EMB;
    for (int i = tid; i < EMB; i += 256) eo[i] = emb_s[i];
}

// =====================================================================
// GEMM v2: C[M x 100] = A[M x K] @ W[K x 100] + bias, optional tanh.
// CTA tile 32 x 100; grid = M/32 (256 CTAs). 200 active compute threads,
// each 4 rows x 4 cols (f32x2 column pairs).
// =====================================================================
template <bool TANH>
__global__ void __launch_bounds__(256) gemm100_kernel(
    const float *__restrict__ A, const float *__restrict__ W,
    const float *__restrict__ bias, float *__restrict__ C, int M, int K)
{
    __shared__ __align__(16) float As[32][33];   // [kk][m]
    __shared__ __align__(16) float Ws[32][104];  // [kk][j]

    const int tid = threadIdx.x;
    const int row0 = blockIdx.x * 32;
    const int tx = tid % 25;   // cols 4*tx .. 4*tx+3
    const int ty = tid / 25;   // rows 4*ty .. 4*ty+3   (ty < 8)
    const bool act = (tid < 200);

    f32x2 acc[4][2];
    #pragma unroll
    for (int r = 0; r < 4; r++) { acc[r][0] = 0ull; acc[r][1] = 0ull; }

    for (int k0 = 0; k0 < K; k0 += 32) {
        for (int e = tid; e < 32 * 32; e += 256) {
            int m = e >> 5, kk = e & 31;
            int k = k0 + kk;
            As[kk][m] = (k < K) ? A[(size_t)(row0 + m) * K + k] : 0.f;
        }
        for (int e = tid; e < 32 * 100; e += 256) {
            int kk = e / 100, j = e % 100;
            int k = k0 + kk;
            Ws[kk][j] = (k < K) ? W[(size_t)k * 100 + j] : 0.f;
        }
        __syncthreads();
        if (act) {
            #pragma unroll
            for (int kk = 0; kk < 32; kk++) {
                f32x2 w0 = *(const f32x2 *)&Ws[kk][4 * tx];
                f32x2 w1 = *(const f32x2 *)&Ws[kk][4 * tx + 2];
                #pragma unroll
                for (int r = 0; r < 4; r++) {
                    float a = As[kk][4 * ty + r];
                    f32x2 aa = pk2(a, a);
                    fma2(acc[r][0], aa, w0);
                    fma2(acc[r][1], aa, w1);
                }
            }
        }
        __syncthreads();
    }
    if (act) {
        float b0 = bias[4 * tx + 0], b1_ = bias[4 * tx + 1];
        float b2_ = bias[4 * tx + 2], b3 = bias[4 * tx + 3];
        #pragma unroll
        for (int r = 0; r < 4; r++) {
            float x0, x1, x2, x3;
            unpk2(acc[r][0], x0, x1);
            unpk2(acc[r][1], x2, x3);
            x0 += b0; x1 += b1_; x2 += b2_; x3 += b3;
            if (TANH) { x0 = tanhf(x0); x1 = tanhf(x1); x2 = tanhf(x2); x3 = tanhf(x3); }
            float4 v = make_float4(x0, x1, x2, x3);
            *(float4 *)&C[(size_t)(row0 + 4 * ty + r) * 100 + 4 * tx] = v;
        }
    }
}

// =====================================================================
// Recurrence: one CTA per batch element, weights live in registers.
// 3 syncs per step (Qt + H-update merged, Qt computed redundantly per alpha).
// =====================================================================
__global__ void __launch_bounds__(512) recurrence_kernel(
    const float *__restrict__ Rw,   // 400 x 100
    const float *__restrict__ Rb,   // 100
    const float *__restrict__ Qw,   // 850 x 100 (rows 750.. are the Rt part)
    const float *__restrict__ E,    // [B*T][100], already includes Q_b
    float *__restrict__ Hall)       // [B*T][400]
{
    __shared__ __align__(16) float sH[HSZ];
    __shared__ float sRt[QS];
    __shared__ __align__(16) float part[1008];   // part[s*100 + j]

    const int tid = threadIdx.x;
    const int b   = blockIdx.x;
    const int jp  = tid % 50;     // output pair: cols 2*jp, 2*jp+1
    const int ks  = tid / 50;     // k-slice
    const bool act = (tid < 500); // 10 slices x 50 pairs

    f32x2 w1r[40];  // R_w slice: k in [40*ks, 40*ks+40)
    f32x2 w2r[10];  // Qw_r slice: k in [10*ks, 10*ks+10)
    if (act) {
        #pragma unroll
        for (int kk = 0; kk < 40; kk++) {
            int k = ks * 40 + kk;
            w1r[kk] = *(const f32x2 *)&Rw[(size_t)k * 100 + 2 * jp];
        }
        #pragma unroll
        for (int kk = 0; kk < 10; kk++) {
            int k = ks * 10 + kk;
            w2r[kk] = *(const f32x2 *)&Qw[(size_t)(750 + k) * 100 + 2 * jp];
        }
    }
    for (int i = tid; i < HSZ; i += 512) sH[i] = 0.f;
    __syncthreads();

    const float *Eb = E + (size_t)b * TT * QS;
    float *Hb = Hall + (size_t)b * TT * HSZ;

    for (int t = 0; t < TT; t++) {
        // --- GEMV1 partials: H(400) -> 100 ---
        if (act) {
            f32x2 a0 = 0ull, a1 = 0ull;
            #pragma unroll
            for (int kk = 0; kk < 40; kk += 2) {
                float h0 = sH[ks * 40 + kk];
                float h1 = sH[ks * 40 + kk + 1];
                fma2(a0, pk2(h0, h0), w1r[kk]);
                fma2(a1, pk2(h1, h1), w1r[kk + 1]);
            }
            *(f32x2 *)&part[ks * 100 + 2 * jp] = add2(a0, a1);
        }
        __syncthreads();
        if (tid < 100) {
            float s = Rb[tid];
            #pragma unroll
            for (int ss = 0; ss < 10; ss++) s += part[ss * 100 + tid];
            sRt[tid] = tanhf(s);
        }
        __syncthreads();
        // --- GEMV2 partials: Rt(100) -> 100 ---
        if (act) {
            f32x2 a = 0ull;
            #pragma unroll
            for (int kk = 0; kk < 10; kk++) {
                float h = sRt[ks * 10 + kk];
                fma2(a, pk2(h, h), w2r[kk]);
            }
            *(f32x2 *)&part[ks * 100 + 2 * jp] = a;
        }
        __syncthreads();
        // --- Qt (redundant per alpha group) + H update + store ---
        if (tid < HSZ) {
            int j = tid % 100;
            float s = Eb[t * QS + j];
            #pragma unroll
            for (int ss = 0; ss < 10; ss++) s += part[ss * 100 + j];
            float q = tanhf(s);
            const float alphas[4] = {0.0f, 0.25f, 0.5f, 0.95f};
            float al = alphas[tid / 100];
            float hn = al * sH[tid] + (1.f - al) * q;
            sH[tid] = hn;
            Hb[t * HSZ + tid] = hn;
        }
        __syncthreads();
    }
}

// =====================================================================
// Logits + softmax. One CTA per batch row.
// =====================================================================
__global__ void __launch_bounds__(256) logits_kernel(
    const float *__restrict__ OutAll, const float *__restrict__ OutW,
    const float *__restrict__ OutB, float *__restrict__ out)
{
    const int b = blockIdx.x, tid = threadIdx.x;
    const float *Ob = OutAll + (size_t)b * (TT * QS);

    float acc[NCLS];
    #pragma unroll
    for (int c = 0; c < NCLS; c++) acc[c] = 0.f;

    for (int i = tid; i < TT * QS; i += 256) {
        float v = Ob[i];
        const float *wr = OutW + (size_t)i * NCLS;
        #pragma unroll
        for (int c = 0; c < NCLS; c++) acc[c] += v * wr[c];
    }
    #pragma unroll
    for (int c = 0; c < NCLS; c++)
        #pragma unroll
        for (int o = 16; o > 0; o >>= 1)
            acc[c] += __shfl_down_sync(0xffffffffu, acc[c], o);

    __shared__ float wpart[8][NCLS];
    int w = tid >> 5, l = tid & 31;
    if (l == 0)
        #pragma unroll
        for (int c = 0; c < NCLS; c++) wpart[w][c] = acc[c];
    __syncthreads();

    __shared__ float slog[NCLS];
    if (tid < NCLS) {
        float s = OutB[tid];
        #pragma unroll
        for (int ww = 0; ww < 8; ww++) s += wpart[ww][tid];
        slog[tid] = s;
    }
    __syncthreads();
    __shared__ float smax, ssum;
    if (tid == 0) {
        float m = slog[0];
        #pragma unroll
        for (int c = 1; c < NCLS; c++) m = fmaxf(m, slog[c]);
        float su = 0.f;
        #pragma unroll
        for (int c = 0; c < NCLS; c++) su += expf(slog[c] - m);
        smax = m; ssum = su;
    }
    __syncthreads();
    if (tid < NCLS) out[(size_t)b * NCLS + tid] = expf(slog[tid] - smax) / ssum;
}

// =====================================================================
extern "C" void kernel_launch(void *const *d_in, const int *in_sizes, int n_in,
                              void *d_out, int out_size)
{
    const float *In     = (const float *)d_in[0];
    const float *conv1w = (const float *)d_in[1];
    const float *conv1b = (const float *)d_in[2];
    const float *conv2w = (const float *)d_in[3];
    const float *conv2b = (const float *)d_in[4];
    const float *Rw     = (const float *)d_in[5];
    const float *Rb     = (const float *)d_in[6];
    const float *Qw     = (const float *)d_in[7];
    const float *Qb     = (const float *)d_in[8];
    const float *Ow     = (const float *)d_in[9];
    const float *Obias  = (const float *)d_in[10];
    const float *OutW   = (const float *)d_in[11];
    const float *OutB   = (const float *)d_in[12];
    float *out = (float *)d_out;

    float *emb, *E, *Hall, *OutAll;
    cudaGetSymbolAddress((void **)&emb,    g_emb);
    cudaGetSymbolAddress((void **)&E,      g_E);
    cudaGetSymbolAddress((void **)&Hall,   g_Hall);
    cudaGetSymbolAddress((void **)&OutAll, g_OutAll);

    // 1) conv embedding for all 8192 images
    conv_embed_kernel<<<NIMG, 256>>>(In, conv1w, conv1b, conv2w, conv2b, emb);
    // 2) E = emb @ Qw[:750] + Qb   (no activation)
    gemm100_kernel<false><<<NIMG / 32, 256>>>(emb, Qw, Qb, E, NIMG, EMB);
    // 3) sequential recurrence (parallel over batch), stores all H_t
    recurrence_kernel<<<BB, 512>>>(Rw, Rb, Qw, E, Hall);
    // 4) OutAll = tanh(Hall @ O_w + O_b)
    gemm100_kernel<true><<<NIMG / 32, 256>>>(Hall, Ow, Obias, OutAll, NIMG, HSZ);
    // 5) logits + softmax
    logits_kernel<<<BB, 256>>>(OutAll, OutW, OutB, out);
}

// round 3
// speedup vs baseline: 1.0982x; 1.0982x over previous
#include <cuda_runtime.h>
#include <cuda_bf16.h>
#include <math.h>

// ---------------- problem constants ----------------
#define BB   128
#define TT   64
#define NIMG (BB*TT)          // 8192
#define HI   50
#define WI   60
#define HO   25
#define WO   30
#define EMB  750
#define QS   100
#define HSZ  400
#define NCLS 10

// ---------------- f32x2 packed helpers ----------------
typedef unsigned long long f32x2;

__device__ __forceinline__ f32x2 pk2(float x, float y) {
    f32x2 r; asm("mov.b64 %0, {%1, %2};" : "=l"(r) : "f"(x), "f"(y)); return r;
}
__device__ __forceinline__ void unpk2(f32x2 v, float &x, float &y) {
    asm("mov.b64 {%0, %1}, %2;" : "=f"(x), "=f"(y) : "l"(v));
}
__device__ __forceinline__ void fma2(f32x2 &d, f32x2 a, f32x2 b) {
    asm("fma.rn.f32x2 %0, %1, %2, %0;" : "+l"(d) : "l"(a), "l"(b));
}
__device__ __forceinline__ f32x2 add2(f32x2 a, f32x2 b) {
    f32x2 d; asm("add.rn.f32x2 %0, %1, %2;" : "=l"(d) : "l"(a), "l"(b)); return d;
}
__device__ __forceinline__ float lky(float x) { return fmaxf(x, 0.01f * x); }

// ---------------- scratch (static device memory; allowed) ----------------
__device__ float g_emb[NIMG * EMB];      // 24.6 MB
__device__ float g_E[NIMG * QS];         //  3.3 MB  (emb @ Qw[:750] + Qb)
__device__ float g_Hall[NIMG * HSZ];     // 13.1 MB
__device__ float g_OutAll[NIMG * QS];    //  3.3 MB

// ---------------- no-op kernels: shift ncu capture onto conv ----------------
__global__ void nop_kernel_a() {}
__global__ void nop_kernel_b() {}
__global__ void nop_kernel_c() {}

// =====================================================================
// Conv: fused conv1(1->16,3x3,s1,p1)+leaky -> conv2(16->1,3x3,s2,p1)+leaky
// One CTA per image. (R2 structure, kept for measurement continuity.)
// =====================================================================
__global__ void __launch_bounds__(256) conv_embed_kernel(
    const float *__restrict__ In,
    const float *__restrict__ w1, const float *__restrict__ b1,
    const float *__restrict__ w2, const float *__restrict__ b2,
    float *__restrict__ emb_out)
{
    __shared__ __align__(16) float pimg[52 * 64];   // [(r+1)][(x+1)], stride 64
    __shared__ f32x2 rb[6][61][8];                  // [row%6][x+1][cpair], col 0 = zero pad
    __shared__ f32x2 sw1[9][8];
    __shared__ f32x2 sw2[9][8];
    __shared__ f32x2 sb1[8];
    __shared__ float emb_s[EMB];

    const int tid = threadIdx.x;
    const float *imgg = In + (size_t)blockIdx.x * (HI * WI);

    for (int i = tid; i < 52 * 64; i += 256) {
        int pr = i >> 6, pc = i & 63;
        int r = pr - 1, x = pc - 1;
        pimg[i] = (r >= 0 && r < HI && x >= 0 && x < WI) ? imgg[r * WI + x] : 0.f;
    }
    if (tid < 72) {
        int tap = tid / 8, cp = tid % 8;
        sw1[tap][cp] = pk2(w1[(2 * cp) * 9 + tap], w1[(2 * cp + 1) * 9 + tap]);
        sw2[tap][cp] = pk2(w2[(2 * cp) * 9 + tap], w2[(2 * cp + 1) * 9 + tap]);
    }
    if (tid < 8) sb1[tid] = pk2(b1[2 * tid], b1[2 * tid + 1]);
    for (int i = tid; i < 6 * 61 * 8; i += 256) ((f32x2 *)rb)[i] = 0ull;
    const float bias2 = b2[0];
    __syncthreads();

    for (int ii = 0; ii < 13; ii++) {
        const int r0 = 4 * ii;
        const int nrows = (ii < 12) ? 4 : 2;
        const int n2rows = nrows >> 1;

        // ---- conv1: rows r0 .. r0+nrows-1 ----
        {
            const int total = nrows * 15 * 8;
            for (int task = tid; task < total; task += 256) {
                int cp = task & 7;
                int rest = task >> 3;
                int xg = rest % 15;
                int rowsel = rest / 15;
                int r = r0 + rowsel;
                int xb = 4 * xg;
                f32x2 a0 = sb1[cp], a1 = a0, a2 = a0, a3 = a0;
                #pragma unroll
                for (int dy = 0; dy < 3; dy++) {
                    const float *row = &pimg[(r + dy) * 64 + xb];
                    float4 v4 = *(const float4 *)row;
                    float2 v2 = *(const float2 *)(row + 4);
                    f32x2 cc0 = pk2(v4.x, v4.x), cc1 = pk2(v4.y, v4.y);
                    f32x2 cc2 = pk2(v4.z, v4.z), cc3 = pk2(v4.w, v4.w);
                    f32x2 cc4 = pk2(v2.x, v2.x), cc5 = pk2(v2.y, v2.y);
                    f32x2 wa = sw1[dy * 3 + 0][cp];
                    f32x2 wb = sw1[dy * 3 + 1][cp];
                    f32x2 wc = sw1[dy * 3 + 2][cp];
                    fma2(a0, cc0, wa); fma2(a0, cc1, wb); fma2(a0, cc2, wc);
                    fma2(a1, cc1, wa); fma2(a1, cc2, wb); fma2(a1, cc3, wc);
                    fma2(a2, cc2, wa); fma2(a2, cc3, wb); fma2(a2, cc4, wc);
                    fma2(a3, cc3, wa); fma2(a3, cc4, wb); fma2(a3, cc5, wc);
                }
                int rs = r % 6;
                float lo, hi;
                unpk2(a0, lo, hi); rb[rs][xb + 1][cp] = pk2(lky(lo), lky(hi));
                unpk2(a1, lo, hi); rb[rs][xb + 2][cp] = pk2(lky(lo), lky(hi));
                unpk2(a2, lo, hi); rb[rs][xb + 3][cp] = pk2(lky(lo), lky(hi));
                unpk2(a3, lo, hi); rb[rs][xb + 4][cp] = pk2(lky(lo), lky(hi));
            }
        }
        __syncthreads();

        // ---- conv2: rows 2*ii .. 2*ii+n2rows-1, shuffle-reduced over cp ----
        {
            const int total2 = n2rows * 30 * 8;
            for (int base = 0; base < total2; base += 256) {
                int task = base + tid;
                bool valid = (task < total2);
                int tt = valid ? task : 0;
                int cp = tt & 7;
                int rest = tt >> 3;
                int x2 = rest % 30;
                int rsel = rest / 30;
                int i2 = 2 * ii + rsel;
                f32x2 acc = 0ull;
                #pragma unroll
                for (int dy = 0; dy < 3; dy++) {
                    int rr = (2 * i2 + dy + 5) % 6;
                    #pragma unroll
                    for (int dx = 0; dx < 3; dx++) {
                        fma2(acc, rb[rr][2 * x2 + dx][cp], sw2[dy * 3 + dx][cp]);
                    }
                }
                float lo, hi; unpk2(acc, lo, hi);
                float s = lo + hi;
                s += __shfl_xor_sync(0xffffffffu, s, 1);
                s += __shfl_xor_sync(0xffffffffu, s, 2);
                s += __shfl_xor_sync(0xffffffffu, s, 4);
                if (valid && cp == 0) emb_s[i2 * 30 + x2] = lky(s + bias2);
            }
        }
        __syncthreads();
    }

    float *eo = emb_out + (size_t)blockIdx.x * EMB;
    for (int i = tid; i < EMB; i += 256) eo[i] = emb_s[i];
}

// =====================================================================
// GEMM (R1 shape): C[M x 100] = A[M x K] @ W[K x 100] + bias, optional tanh.
// CTA tile 64 x 100; 200 active threads, each 8 rows x 4 cols (f32x2 pairs).
// =====================================================================
template <bool TANH>
__global__ void __launch_bounds__(256) gemm100_kernel(
    const float *__restrict__ A, const float *__restrict__ W,
    const float *__restrict__ bias, float *__restrict__ C, int M, int K)
{
    __shared__ __align__(16) float As[32][65];   // [kk][m]
    __shared__ __align__(16) float Ws[32][104];  // [kk][j]

    const int tid = threadIdx.x;
    const int row0 = blockIdx.x * 64;
    const int tx = tid % 25;   // cols 4*tx .. 4*tx+3
    const int ty = tid / 25;   // rows 8*ty .. 8*ty+7
    const bool act = (tid < 200);

    f32x2 acc[8][2];
    #pragma unroll
    for (int r = 0; r < 8; r++) { acc[r][0] = 0ull; acc[r][1] = 0ull; }

    for (int k0 = 0; k0 < K; k0 += 32) {
        for (int e = tid; e < 64 * 32; e += 256) {
            int m = e >> 5, kk = e & 31;
            int k = k0 + kk;
            As[kk][m] = (k < K) ? A[(size_t)(row0 + m) * K + k] : 0.f;
        }
        for (int e = tid; e < 32 * 100; e += 256) {
            int kk = e / 100, j = e % 100;
            int k = k0 + kk;
            Ws[kk][j] = (k < K) ? W[(size_t)k * 100 + j] : 0.f;
        }
        __syncthreads();
        if (act) {
            #pragma unroll
            for (int kk = 0; kk < 32; kk++) {
                f32x2 w0 = *(const f32x2 *)&Ws[kk][4 * tx];
                f32x2 w1 = *(const f32x2 *)&Ws[kk][4 * tx + 2];
                #pragma unroll
                for (int r = 0; r < 8; r++) {
                    float a = As[kk][8 * ty + r];
                    f32x2 aa = pk2(a, a);
                    fma2(acc[r][0], aa, w0);
                    fma2(acc[r][1], aa, w1);
                }
            }
        }
        __syncthreads();
    }
    if (act) {
        float b0 = bias[4 * tx + 0], b1_ = bias[4 * tx + 1];
        float b2_ = bias[4 * tx + 2], b3 = bias[4 * tx + 3];
        #pragma unroll
        for (int r = 0; r < 8; r++) {
            float x0, x1, x2, x3;
            unpk2(acc[r][0], x0, x1);
            unpk2(acc[r][1], x2, x3);
            x0 += b0; x1 += b1_; x2 += b2_; x3 += b3;
            if (TANH) { x0 = tanhf(x0); x1 = tanhf(x1); x2 = tanhf(x2); x3 = tanhf(x3); }
            float4 v = make_float4(x0, x1, x2, x3);
            *(float4 *)&C[(size_t)(row0 + 8 * ty + r) * 100 + 4 * tx] = v;
        }
    }
}

// =====================================================================
// Recurrence: one CTA per batch element, weights live in registers.
// =====================================================================
__global__ void __launch_bounds__(512) recurrence_kernel(
    const float *__restrict__ Rw,   // 400 x 100
    const float *__restrict__ Rb,   // 100
    const float *__restrict__ Qw,   // 850 x 100 (rows 750.. are the Rt part)
    const float *__restrict__ E,    // [B*T][100], already includes Q_b
    float *__restrict__ Hall)       // [B*T][400]
{
    __shared__ __align__(16) float sH[HSZ];
    __shared__ float sRt[QS];
    __shared__ __align__(16) float part[1008];   // part[s*100 + j]

    const int tid = threadIdx.x;
    const int b   = blockIdx.x;
    const int jp  = tid % 50;
    const int ks  = tid / 50;
    const bool act = (tid < 500);

    f32x2 w1r[40];
    f32x2 w2r[10];
    if (act) {
        #pragma unroll
        for (int kk = 0; kk < 40; kk++) {
            int k = ks * 40 + kk;
            w1r[kk] = *(const f32x2 *)&Rw[(size_t)k * 100 + 2 * jp];
        }
        #pragma unroll
        for (int kk = 0; kk < 10; kk++) {
            int k = ks * 10 + kk;
            w2r[kk] = *(const f32x2 *)&Qw[(size_t)(750 + k) * 100 + 2 * jp];
        }
    }
    for (int i = tid; i < HSZ; i += 512) sH[i] = 0.f;
    __syncthreads();

    const float *Eb = E + (size_t)b * TT * QS;
    float *Hb = Hall + (size_t)b * TT * HSZ;

    for (int t = 0; t < TT; t++) {
        if (act) {
            f32x2 a0 = 0ull, a1 = 0ull;
            #pragma unroll
            for (int kk = 0; kk < 40; kk += 2) {
                float h0 = sH[ks * 40 + kk];
                float h1 = sH[ks * 40 + kk + 1];
                fma2(a0, pk2(h0, h0), w1r[kk]);
                fma2(a1, pk2(h1, h1), w1r[kk + 1]);
            }
            *(f32x2 *)&part[ks * 100 + 2 * jp] = add2(a0, a1);
        }
        __syncthreads();
        if (tid < 100) {
            float s = Rb[tid];
            #pragma unroll
            for (int ss = 0; ss < 10; ss++) s += part[ss * 100 + tid];
            sRt[tid] = tanhf(s);
        }
        __syncthreads();
        if (act) {
            f32x2 a = 0ull;
            #pragma unroll
            for (int kk = 0; kk < 10; kk++) {
                float h = sRt[ks * 10 + kk];
                fma2(a, pk2(h, h), w2r[kk]);
            }
            *(f32x2 *)&part[ks * 100 + 2 * jp] = a;
        }
        __syncthreads();
        if (tid < HSZ) {
            int j = tid % 100;
            float s = Eb[t * QS + j];
            #pragma unroll
            for (int ss = 0; ss < 10; ss++) s += part[ss * 100 + j];
            float q = tanhf(s);
            const float alphas[4] = {0.0f, 0.25f, 0.5f, 0.95f};
            float al = alphas[tid / 100];
            float hn = al * sH[tid] + (1.f - al) * q;
            sH[tid] = hn;
            Hb[t * HSZ + tid] = hn;
        }
        __syncthreads();
    }
}

// =====================================================================
// Logits + softmax. One CTA per batch row.
// =====================================================================
__global__ void __launch_bounds__(256) logits_kernel(
    const float *__restrict__ OutAll, const float *__restrict__ OutW,
    const float *__restrict__ OutB, float *__restrict__ out)
{
    const int b = blockIdx.x, tid = threadIdx.x;
    const float *Ob = OutAll + (size_t)b * (TT * QS);

    float acc[NCLS];
    #pragma unroll
    for (int c = 0; c < NCLS; c++) acc[c] = 0.f;

    for (int i = tid; i < TT * QS; i += 256) {
        float v = Ob[i];
        const float *wr = OutW + (size_t)i * NCLS;
        #pragma unroll
        for (int c = 0; c < NCLS; c++) acc[c] += v * wr[c];
    }
    #pragma unroll
    for (int c = 0; c < NCLS; c++)
        #pragma unroll
        for (int o = 16; o > 0; o >>= 1)
            acc[c] += __shfl_down_sync(0xffffffffu, acc[c], o);

    __shared__ float wpart[8][NCLS];
    int w = tid >> 5, l = tid & 31;
    if (l == 0)
        #pragma unroll
        for (int c = 0; c < NCLS; c++) wpart[w][c] = acc[c];
    __syncthreads();

    __shared__ float slog[NCLS];
    if (tid < NCLS) {
        float s = OutB[tid];
        #pragma unroll
        for (int ww = 0; ww < 8; ww++) s += wpart[ww][tid];
        slog[tid] = s;
    }
    __syncthreads();
    __shared__ float smax, ssum;
    if (tid == 0) {
        float m = slog[0];
        #pragma unroll
        for (int c = 1; c < NCLS; c++) m = fmaxf(m, slog[c]);
        float su = 0.f;
        #pragma unroll
        for (int c = 0; c < NCLS; c++) su += expf(slog[c] - m);
        smax = m; ssum = su;
    }
    __syncthreads();
    if (tid < NCLS) out[(size_t)b * NCLS + tid] = expf(slog[tid] - smax) / ssum;
}

// =====================================================================
extern "C" void kernel_launch(void *const *d_in, const int *in_sizes, int n_in,
                              void *d_out, int out_size)
{
    const float *In     = (const float *)d_in[0];
    const float *conv1w = (const float *)d_in[1];
    const float *conv1b = (const float *)d_in[2];
    const float *conv2w = (const float *)d_in[3];
    const float *conv2b = (const float *)d_in[4];
    const float *Rw     = (const float *)d_in[5];
    const float *Rb     = (const float *)d_in[6];
    const float *Qw     = (const float *)d_in[7];
    const float *Qb     = (const float *)d_in[8];
    const float *Ow     = (const float *)d_in[9];
    const float *Obias  = (const float *)d_in[10];
    const float *OutW   = (const float *)d_in[11];
    const float *OutB   = (const float *)d_in[12];
    float *out = (float *)d_out;

    float *emb, *E, *Hall, *OutAll;
    cudaGetSymbolAddress((void **)&emb,    g_emb);
    cudaGetSymbolAddress((void **)&E,      g_E);
    cudaGetSymbolAddress((void **)&Hall,   g_Hall);
    cudaGetSymbolAddress((void **)&OutAll, g_OutAll);

    // position-shifters so the ncu capture (fixed skip count) lands on conv
    nop_kernel_a<<<1, 32>>>();
    nop_kernel_b<<<1, 32>>>();
    nop_kernel_c<<<1, 32>>>();

    // 1) conv embedding for all 8192 images
    conv_embed_kernel<<<NIMG, 256>>>(In, conv1w, conv1b, conv2w, conv2b, emb);
    // 2) E = emb @ Qw[:750] + Qb   (no activation)
    gemm100_kernel<false><<<NIMG / 64, 256>>>(emb, Qw, Qb, E, NIMG, EMB);
    // 3) sequential recurrence (parallel over batch), stores all H_t
    recurrence_kernel<<<BB, 512>>>(Rw, Rb, Qw, E, Hall);
    // 4) OutAll = tanh(Hall @ O_w + O_b)
    gemm100_kernel<true><<<NIMG / 64, 256>>>(Hall, Ow, Obias, OutAll, NIMG, HSZ);
    // 5) logits + softmax
    logits_kernel<<<BB, 256>>>(OutAll, OutW, OutB, out);
}

// round 5
// speedup vs baseline: 1.4025x; 1.2771x over previous
#include <cuda_runtime.h>
#include <cuda_bf16.h>
#include <math.h>

// ---------------- problem constants ----------------
#define BB   128
#define TT   64
#define NIMG (BB*TT)          // 8192
#define HI   50
#define WI   60
#define HO   25
#define WO   30
#define EMB  750
#define QS   100
#define HSZ  400
#define NCLS 10

// ---------------- f32x2 packed helpers ----------------
typedef unsigned long long f32x2;

__device__ __forceinline__ f32x2 pk2(float x, float y) {
    f32x2 r; asm("mov.b64 %0, {%1, %2};" : "=l"(r) : "f"(x), "f"(y)); return r;
}
__device__ __forceinline__ void unpk2(f32x2 v, float &x, float &y) {
    asm("mov.b64 {%0, %1}, %2;" : "=f"(x), "=f"(y) : "l"(v));
}
__device__ __forceinline__ void fma2(f32x2 &d, f32x2 a, f32x2 b) {
    asm("fma.rn.f32x2 %0, %1, %2, %0;" : "+l"(d) : "l"(a), "l"(b));
}
__device__ __forceinline__ f32x2 mul2(f32x2 a, f32x2 b) {
    f32x2 d; asm("mul.rn.f32x2 %0, %1, %2;" : "=l"(d) : "l"(a), "l"(b)); return d;
}
__device__ __forceinline__ f32x2 add2(f32x2 a, f32x2 b) {
    f32x2 d; asm("add.rn.f32x2 %0, %1, %2;" : "=l"(d) : "l"(a), "l"(b)); return d;
}
__device__ __forceinline__ float lky(float x) { return fmaxf(x, 0.01f * x); }
// packed leaky: 0.505*x + 0.495*|x|  (==x for x>=0, 0.01x for x<0)
__device__ __forceinline__ f32x2 lky2(f32x2 x) {
    f32x2 a = x & 0x7FFFFFFF7FFFFFFFULL;
    f32x2 r = mul2(x, pk2(0.505f, 0.505f));
    fma2(r, a, pk2(0.495f, 0.495f));
    return r;
}

// ---------------- scratch (static device memory; allowed) ----------------
__device__ float g_emb[NIMG * EMB];      // 24.6 MB
__device__ float g_E[NIMG * QS];         //  3.3 MB
__device__ float g_Hall[NIMG * HSZ];     // 13.1 MB
__device__ float g_OutAll[NIMG * QS];    //  3.3 MB

// ---------------- no-op kernels: keep ncu capture on conv ----------------
__global__ void nop_kernel_a() {}
__global__ void nop_kernel_b() {}
__global__ void nop_kernel_c() {}

// =====================================================================
// Conv v3b: register-resident fused conv1+leaky -> conv2+leaky.
// One CTA per image. Warp w owns conv2 rows i2 = w, w+8, w+16[, 24].
// Lane = (cp = lane&7: channel pair, xq = lane>>3: x-quarter).
// v[j] = conv1 output at x1 = 16*xq + j (j = 0..15), leaky applied.
// Left halo v[-1] comes from neighbor lane via shfl_up(v[15], 8).
// =====================================================================
__global__ void __launch_bounds__(256, 2) conv_embed_kernel(
    const float *__restrict__ In,
    const float *__restrict__ w1, const float *__restrict__ b1,
    const float *__restrict__ w2, const float *__restrict__ b2,
    float *__restrict__ emb_out)
{
    __shared__ __align__(16) float pimg[52 * 64 + 16]; // padded image + tail pad
    __shared__ f32x2 sw1[9][8];
    __shared__ f32x2 sw2[9][8];
    __shared__ f32x2 sb1[8];
    __shared__ float emb_s[EMB];

    const int tid = threadIdx.x;
    const int wid = tid >> 5;
    const int lane = tid & 31;
    const int cp = lane & 7;
    const int xq = lane >> 3;
    const float *imgg = In + (size_t)blockIdx.x * (HI * WI);

    for (int i = tid; i < 52 * 64 + 16; i += 256) {
        int pr = i >> 6, pc = i & 63;
        int r = pr - 1, x = pc - 1;
        pimg[i] = (i < 52 * 64 && r >= 0 && r < HI && x >= 0 && x < WI)
                  ? imgg[r * WI + x] : 0.f;
    }
    if (tid < 72) {
        int tap = tid / 8, c = tid % 8;
        sw1[tap][c] = pk2(w1[(2 * c) * 9 + tap], w1[(2 * c + 1) * 9 + tap]);
        sw2[tap][c] = pk2(w2[(2 * c) * 9 + tap], w2[(2 * c + 1) * 9 + tap]);
    }
    if (tid < 8) sb1[tid] = pk2(b1[2 * tid], b1[2 * tid + 1]);
    const float bias2 = b2[0];
    __syncthreads();

    // per-thread register copies of conv1 weights + bias (for its cp)
    f32x2 rw1[9];
    #pragma unroll
    for (int t = 0; t < 9; t++) rw1[t] = sw1[t][cp];
    const f32x2 rb1 = sb1[cp];

    const int n_out = (xq == 3) ? 6 : 8;
    const int pxb = 16 * xq;   // padded col base; v[j] is conv1 at x1 = 16*xq + j

    #pragma unroll 1
    for (int i2 = wid; i2 < HO; i2 += 8) {
        f32x2 acc[8];
        #pragma unroll
        for (int o = 0; o < 8; o++) acc[o] = 0ull;

        #pragma unroll
        for (int dy2 = 0; dy2 < 3; dy2++) {
            const int r = 2 * i2 - 1 + dy2;           // conv1 row
            if (r < 0) continue;                       // conv2 top zero pad

            // ---- conv1 row r: v[j] = conv1(x1 = 16*xq + j), j = 0..15 ----
            // needs padded cols 16*xq + j .. +j+2  ->  f[0..17]
            f32x2 v[16];
            #pragma unroll
            for (int j = 0; j < 16; j++) v[j] = rb1;
            #pragma unroll
            for (int dy = 0; dy < 3; dy++) {
                const float *rowp = &pimg[(r + dy) * 64 + pxb];
                float4 q0 = *(const float4 *)(rowp + 0);
                float4 q1 = *(const float4 *)(rowp + 4);
                float4 q2 = *(const float4 *)(rowp + 8);
                float4 q3 = *(const float4 *)(rowp + 12);
                float2 q4 = *(const float2 *)(rowp + 16);
                float f[18] = {q0.x,q0.y,q0.z,q0.w, q1.x,q1.y,q1.z,q1.w,
                               q2.x,q2.y,q2.z,q2.w, q3.x,q3.y,q3.z,q3.w,
                               q4.x,q4.y};
                f32x2 wa = rw1[dy * 3 + 0], wb = rw1[dy * 3 + 1], wc = rw1[dy * 3 + 2];
                #pragma unroll
                for (int j = 0; j < 16; j++) {
                    fma2(v[j], pk2(f[j + 0], f[j + 0]), wa);
                    fma2(v[j], pk2(f[j + 1], f[j + 1]), wb);
                    fma2(v[j], pk2(f[j + 2], f[j + 2]), wc);
                }
            }
            #pragma unroll
            for (int j = 0; j < 16; j++) v[j] = lky2(v[j]);

            // left halo: conv1 at x1 = 16*xq - 1 (== neighbor's v[15])
            f32x2 vm1 = __shfl_up_sync(0xffffffffu, v[15], 8);
            if (xq == 0) vm1 = 0ull;                   // conv2 left zero pad (x1 = -1)

            // ---- conv2 accumulate: x2 = 8*xq + o uses v[2o-1], v[2o], v[2o+1] ----
            f32x2 w2a = sw2[dy2 * 3 + 0][cp];
            f32x2 w2b = sw2[dy2 * 3 + 1][cp];
            f32x2 w2c = sw2[dy2 * 3 + 2][cp];
            fma2(acc[0], vm1,  w2a);
            fma2(acc[0], v[0], w2b);
            fma2(acc[0], v[1], w2c);
            #pragma unroll
            for (int o = 1; o < 8; o++) {
                fma2(acc[o], v[2 * o - 1], w2a);
                fma2(acc[o], v[2 * o + 0], w2b);
                fma2(acc[o], v[2 * o + 1], w2c);
            }
        }

        // ---- reduce over 16 channels (f32x2 halves + cp lanes) ----
        #pragma unroll
        for (int o = 0; o < 8; o++) {
            float lo, hi; unpk2(acc[o], lo, hi);
            float s = lo + hi;
            s += __shfl_xor_sync(0xffffffffu, s, 1);
            s += __shfl_xor_sync(0xffffffffu, s, 2);
            s += __shfl_xor_sync(0xffffffffu, s, 4);
            if (cp == 0 && o < n_out)
                emb_s[i2 * 30 + 8 * xq + o] = lky(s + bias2);
        }
    }
    __syncthreads();

    float *eo = emb_out + (size_t)blockIdx.x * EMB;
    for (int i = tid; i < EMB; i += 256) eo[i] = emb_s[i];
}

// =====================================================================
// GEMM (R1 shape): C[M x 100] = A[M x K] @ W[K x 100] + bias, optional tanh.
// CTA tile 64 x 100; 200 active threads, each 8 rows x 4 cols (f32x2 pairs).
// =====================================================================
template <bool TANH>
__global__ void __launch_bounds__(256) gemm100_kernel(
    const float *__restrict__ A, const float *__restrict__ W,
    const float *__restrict__ bias, float *__restrict__ C, int M, int K)
{
    __shared__ __align__(16) float As[32][65];   // [kk][m]
    __shared__ __align__(16) float Ws[32][104];  // [kk][j]

    const int tid = threadIdx.x;
    const int row0 = blockIdx.x * 64;
    const int tx = tid % 25;
    const int ty = tid / 25;
    const bool act = (tid < 200);

    f32x2 acc[8][2];
    #pragma unroll
    for (int r = 0; r < 8; r++) { acc[r][0] = 0ull; acc[r][1] = 0ull; }

    for (int k0 = 0; k0 < K; k0 += 32) {
        for (int e = tid; e < 64 * 32; e += 256) {
            int m = e >> 5, kk = e & 31;
            int k = k0 + kk;
            As[kk][m] = (k < K) ? A[(size_t)(row0 + m) * K + k] : 0.f;
        }
        for (int e = tid; e < 32 * 100; e += 256) {
            int kk = e / 100, j = e % 100;
            int k = k0 + kk;
            Ws[kk][j] = (k < K) ? W[(size_t)k * 100 + j] : 0.f;
        }
        __syncthreads();
        if (act) {
            #pragma unroll
            for (int kk = 0; kk < 32; kk++) {
                f32x2 w0 = *(const f32x2 *)&Ws[kk][4 * tx];
                f32x2 w1 = *(const f32x2 *)&Ws[kk][4 * tx + 2];
                #pragma unroll
                for (int r = 0; r < 8; r++) {
                    float a = As[kk][8 * ty + r];
                    f32x2 aa = pk2(a, a);
                    fma2(acc[r][0], aa, w0);
                    fma2(acc[r][1], aa, w1);
                }
            }
        }
        __syncthreads();
    }
    if (act) {
        float b0 = bias[4 * tx + 0], b1_ = bias[4 * tx + 1];
        float b2_ = bias[4 * tx + 2], b3 = bias[4 * tx + 3];
        #pragma unroll
        for (int r = 0; r < 8; r++) {
            float x0, x1, x2, x3;
            unpk2(acc[r][0], x0, x1);
            unpk2(acc[r][1], x2, x3);
            x0 += b0; x1 += b1_; x2 += b2_; x3 += b3;
            if (TANH) { x0 = tanhf(x0); x1 = tanhf(x1); x2 = tanhf(x2); x3 = tanhf(x3); }
            float4 v = make_float4(x0, x1, x2, x3);
            *(float4 *)&C[(size_t)(row0 + 8 * ty + r) * 100 + 4 * tx] = v;
        }
    }
}

// =====================================================================
// Recurrence: one CTA per batch element, weights live in registers.
// =====================================================================
__global__ void __launch_bounds__(512) recurrence_kernel(
    const float *__restrict__ Rw, const float *__restrict__ Rb,
    const float *__restrict__ Qw, const float *__restrict__ E,
    float *__restrict__ Hall)
{
    __shared__ __align__(16) float sH[HSZ];
    __shared__ float sRt[QS];
    __shared__ __align__(16) float part[1008];

    const int tid = threadIdx.x;
    const int b   = blockIdx.x;
    const int jp  = tid % 50;
    const int ks  = tid / 50;
    const bool act = (tid < 500);

    f32x2 w1r[40];
    f32x2 w2r[10];
    if (act) {
        #pragma unroll
        for (int kk = 0; kk < 40; kk++) {
            int k = ks * 40 + kk;
            w1r[kk] = *(const f32x2 *)&Rw[(size_t)k * 100 + 2 * jp];
        }
        #pragma unroll
        for (int kk = 0; kk < 10; kk++) {
            int k = ks * 10 + kk;
            w2r[kk] = *(const f32x2 *)&Qw[(size_t)(750 + k) * 100 + 2 * jp];
        }
    }
    for (int i = tid; i < HSZ; i += 512) sH[i] = 0.f;
    __syncthreads();

    const float *Eb = E + (size_t)b * TT * QS;
    float *Hb = Hall + (size_t)b * TT * HSZ;

    for (int t = 0; t < TT; t++) {
        if (act) {
            f32x2 a0 = 0ull, a1 = 0ull;
            #pragma unroll
            for (int kk = 0; kk < 40; kk += 2) {
                float h0 = sH[ks * 40 + kk];
                float h1 = sH[ks * 40 + kk + 1];
                fma2(a0, pk2(h0, h0), w1r[kk]);
                fma2(a1, pk2(h1, h1), w1r[kk + 1]);
            }
            *(f32x2 *)&part[ks * 100 + 2 * jp] = add2(a0, a1);
        }
        __syncthreads();
        if (tid < 100) {
            float s = Rb[tid];
            #pragma unroll
            for (int ss = 0; ss < 10; ss++) s += part[ss * 100 + tid];
            sRt[tid] = tanhf(s);
        }
        __syncthreads();
        if (act) {
            f32x2 a = 0ull;
            #pragma unroll
            for (int kk = 0; kk < 10; kk++) {
                float h = sRt[ks * 10 + kk];
                fma2(a, pk2(h, h), w2r[kk]);
            }
            *(f32x2 *)&part[ks * 100 + 2 * jp] = a;
        }
        __syncthreads();
        if (tid < HSZ) {
            int j = tid % 100;
            float s = Eb[t * QS + j];
            #pragma unroll
            for (int ss = 0; ss < 10; ss++) s += part[ss * 100 + j];
            float q = tanhf(s);
            const float alphas[4] = {0.0f, 0.25f, 0.5f, 0.95f};
            float al = alphas[tid / 100];
            float hn = al * sH[tid] + (1.f - al) * q;
            sH[tid] = hn;
            Hb[t * HSZ + tid] = hn;
        }
        __syncthreads();
    }
}

// =====================================================================
// Logits + softmax. One CTA per batch row.
// =====================================================================
__global__ void __launch_bounds__(256) logits_kernel(
    const float *__restrict__ OutAll, const float *__restrict__ OutW,
    const float *__restrict__ OutB, float *__restrict__ out)
{
    const int b = blockIdx.x, tid = threadIdx.x;
    const float *Ob = OutAll + (size_t)b * (TT * QS);

    float acc[NCLS];
    #pragma unroll
    for (int c = 0; c < NCLS; c++) acc[c] = 0.f;

    for (int i = tid; i < TT * QS; i += 256) {
        float v = Ob[i];
        const float *wr = OutW + (size_t)i * NCLS;
        #pragma unroll
        for (int c = 0; c < NCLS; c++) acc[c] += v * wr[c];
    }
    #pragma unroll
    for (int c = 0; c < NCLS; c++)
        #pragma unroll
        for (int o = 16; o > 0; o >>= 1)
            acc[c] += __shfl_down_sync(0xffffffffu, acc[c], o);

    __shared__ float wpart[8][NCLS];
    int w = tid >> 5, l = tid & 31;
    if (l == 0)
        #pragma unroll
        for (int c = 0; c < NCLS; c++) wpart[w][c] = acc[c];
    __syncthreads();

    __shared__ float slog[NCLS];
    if (tid < NCLS) {
        float s = OutB[tid];
        #pragma unroll
        for (int ww = 0; ww < 8; ww++) s += wpart[ww][tid];
        slog[tid] = s;
    }
    __syncthreads();
    __shared__ float smax, ssum;
    if (tid == 0) {
        float m = slog[0];
        #pragma unroll
        for (int c = 1; c < NCLS; c++) m = fmaxf(m, slog[c]);
        float su = 0.f;
        #pragma unroll
        for (int c = 0; c < NCLS; c++) su += expf(slog[c] - m);
        smax = m; ssum = su;
    }
    __syncthreads();
    if (tid < NCLS) out[(size_t)b * NCLS + tid] = expf(slog[tid] - smax) / ssum;
}

// =====================================================================
extern "C" void kernel_launch(void *const *d_in, const int *in_sizes, int n_in,
                              void *d_out, int out_size)
{
    const float *In     = (const float *)d_in[0];
    const float *conv1w = (const float *)d_in[1];
    const float *conv1b = (const float *)d_in[2];
    const float *conv2w = (const float *)d_in[3];
    const float *conv2b = (const float *)d_in[4];
    const float *Rw     = (const float *)d_in[5];
    const float *Rb     = (const float *)d_in[6];
    const float *Qw     = (const float *)d_in[7];
    const float *Qb     = (const float *)d_in[8];
    const float *Ow     = (const float *)d_in[9];
    const float *Obias  = (const float *)d_in[10];
    const float *OutW   = (const float *)d_in[11];
    const float *OutB   = (const float *)d_in[12];
    float *out = (float *)d_out;

    float *emb, *E, *Hall, *OutAll;
    cudaGetSymbolAddress((void **)&emb,    g_emb);
    cudaGetSymbolAddress((void **)&E,      g_E);
    cudaGetSymbolAddress((void **)&Hall,   g_Hall);
    cudaGetSymbolAddress((void **)&OutAll, g_OutAll);

    // position-shifters so ncu capture lands on conv
    nop_kernel_a<<<1, 32>>>();
    nop_kernel_b<<<1, 32>>>();
    nop_kernel_c<<<1, 32>>>();

    conv_embed_kernel<<<NIMG, 256>>>(In, conv1w, conv1b, conv2w, conv2b, emb);
    gemm100_kernel<false><<<NIMG / 64, 256>>>(emb, Qw, Qb, E, NIMG, EMB);
    recurrence_kernel<<<BB, 512>>>(Rw, Rb, Qw, E, Hall);
    gemm100_kernel<true><<<NIMG / 64, 256>>>(Hall, Ow, Obias, OutAll, NIMG, HSZ);
    logits_kernel<<<BB, 256>>>(OutAll, OutW, OutB, out);
}

// round 6
// speedup vs baseline: 1.6952x; 1.2087x over previous
#include <cuda_runtime.h>
#include <cuda_bf16.h>
#include <math.h>

// ---------------- problem constants ----------------
#define BB   128
#define TT   64
#define NIMG (BB*TT)          // 8192
#define HI   50
#define WI   60
#define HO   25
#define WO   30
#define EMB  750
#define QS   100
#define HSZ  400
#define NCLS 10

// ---------------- f32x2 packed helpers ----------------
typedef unsigned long long f32x2;

__device__ __forceinline__ f32x2 pk2(float x, float y) {
    f32x2 r; asm("mov.b64 %0, {%1, %2};" : "=l"(r) : "f"(x), "f"(y)); return r;
}
__device__ __forceinline__ void unpk2(f32x2 v, float &x, float &y) {
    asm("mov.b64 {%0, %1}, %2;" : "=f"(x), "=f"(y) : "l"(v));
}
__device__ __forceinline__ void fma2(f32x2 &d, f32x2 a, f32x2 b) {
    asm("fma.rn.f32x2 %0, %1, %2, %0;" : "+l"(d) : "l"(a), "l"(b));
}
__device__ __forceinline__ f32x2 mul2(f32x2 a, f32x2 b) {
    f32x2 d; asm("mul.rn.f32x2 %0, %1, %2;" : "=l"(d) : "l"(a), "l"(b)); return d;
}
__device__ __forceinline__ f32x2 add2(f32x2 a, f32x2 b) {
    f32x2 d; asm("add.rn.f32x2 %0, %1, %2;" : "=l"(d) : "l"(a), "l"(b)); return d;
}
__device__ __forceinline__ float lky(float x) { return fmaxf(x, 0.01f * x); }
// packed leaky: 0.505*x + 0.495*|x|
__device__ __forceinline__ f32x2 lky2(f32x2 x) {
    f32x2 a = x & 0x7FFFFFFF7FFFFFFFULL;
    f32x2 r = mul2(x, pk2(0.505f, 0.505f));
    fma2(r, a, pk2(0.495f, 0.495f));
    return r;
}

// ---------------- scratch (static device memory; allowed) ----------------
__device__ float g_emb[NIMG * EMB];          // 24.6 MB
__device__ float g_E[2 * NIMG * QS];         //  6.6 MB  (two K-split halves)
__device__ float g_Hall[NIMG * HSZ];         // 13.1 MB
__device__ float g_OutAll[2 * NIMG * QS];    //  6.6 MB  (two K-split halves)

// ---------------- no-op kernels: keep ncu capture on conv ----------------
__global__ void nop_kernel_a() {}
__global__ void nop_kernel_b() {}
__global__ void nop_kernel_c() {}

// =====================================================================
// Conv v4: register-resident fused conv1+leaky -> conv2+leaky, x-chunked.
// One CTA per image, 3 CTAs/SM target. Warp w owns i2 = w, w+8, w+16[,24].
// Lane = (cp = lane&7, xq = lane>>3). Per (i2, dy2) row:
//   phase1: vc[j] = conv1(x = 16xq+8+j), j=0..7  (upper chunk, incl. v15)
//   shfl:   vm1   = neighbor's v15 (conv1 at 16xq-1)
//   phase2: vd[j] = conv1(x = 16xq+j),  j=0..7  (lower chunk)
// conv2 x2 = 8xq+o uses v[2o-1], v[2o], v[2o+1].
// =====================================================================
__global__ void __launch_bounds__(256, 3) conv_embed_kernel(
    const float *__restrict__ In,
    const float *__restrict__ w1, const float *__restrict__ b1,
    const float *__restrict__ w2, const float *__restrict__ b2,
    float *__restrict__ emb_out)
{
    __shared__ __align__(16) float pimg[52 * 64 + 16];
    __shared__ f32x2 sw1[9][8];
    __shared__ f32x2 sw2[9][8];
    __shared__ f32x2 sb1[8];
    __shared__ float emb_s[EMB];

    const int tid = threadIdx.x;
    const int wid = tid >> 5;
    const int lane = tid & 31;
    const int cp = lane & 7;
    const int xq = lane >> 3;
    const float *imgg = In + (size_t)blockIdx.x * (HI * WI);

    for (int i = tid; i < 52 * 64 + 16; i += 256) {
        int pr = i >> 6, pc = i & 63;
        int r = pr - 1, x = pc - 1;
        pimg[i] = (i < 52 * 64 && r >= 0 && r < HI && x >= 0 && x < WI)
                  ? imgg[r * WI + x] : 0.f;
    }
    if (tid < 72) {
        int tap = tid / 8, c = tid % 8;
        sw1[tap][c] = pk2(w1[(2 * c) * 9 + tap], w1[(2 * c + 1) * 9 + tap]);
        sw2[tap][c] = pk2(w2[(2 * c) * 9 + tap], w2[(2 * c + 1) * 9 + tap]);
    }
    if (tid < 8) sb1[tid] = pk2(b1[2 * tid], b1[2 * tid + 1]);
    const float bias2 = b2[0];
    __syncthreads();

    f32x2 rw1[9];
    #pragma unroll
    for (int t = 0; t < 9; t++) rw1[t] = sw1[t][cp];
    const f32x2 rb1 = sb1[cp];

    const int n_out = (xq == 3) ? 6 : 8;
    const int pxb = 16 * xq;

    #pragma unroll 1
    for (int i2 = wid; i2 < HO; i2 += 8) {
        f32x2 acc[8];
        #pragma unroll
        for (int o = 0; o < 8; o++) acc[o] = 0ull;

        #pragma unroll 1
        for (int dy2 = 0; dy2 < 3; dy2++) {
            const int r = 2 * i2 - 1 + dy2;           // conv1 row
            const bool rvalid = (r >= 0);              // warp-uniform
            f32x2 w2a = sw2[dy2 * 3 + 0][cp];
            f32x2 w2b = sw2[dy2 * 3 + 1][cp];
            f32x2 w2c = sw2[dy2 * 3 + 2][cp];
            f32x2 vtop = 0ull;

            if (rvalid) {
                // ---- phase 1: upper chunk vc[j] = conv1(16xq+8+j) ----
                f32x2 vc[8];
                #pragma unroll
                for (int j = 0; j < 8; j++) vc[j] = rb1;
                #pragma unroll
                for (int dy = 0; dy < 3; dy++) {
                    const float *rowp = &pimg[(r + dy) * 64 + pxb + 8];
                    float4 q0 = *(const float4 *)(rowp + 0);
                    float4 q1 = *(const float4 *)(rowp + 4);
                    float2 q2 = *(const float2 *)(rowp + 8);
                    float f[10] = {q0.x,q0.y,q0.z,q0.w, q1.x,q1.y,q1.z,q1.w,
                                   q2.x,q2.y};
                    f32x2 wa = rw1[dy*3+0], wb = rw1[dy*3+1], wc = rw1[dy*3+2];
                    #pragma unroll
                    for (int j = 0; j < 8; j++) {
                        fma2(vc[j], pk2(f[j+0], f[j+0]), wa);
                        fma2(vc[j], pk2(f[j+1], f[j+1]), wb);
                        fma2(vc[j], pk2(f[j+2], f[j+2]), wc);
                    }
                }
                #pragma unroll
                for (int j = 0; j < 8; j++) vc[j] = lky2(vc[j]);
                // conv2 upper outputs: o=4..7 ; o=4 gets its v7 term in phase 2
                fma2(acc[4], vc[0], w2b); fma2(acc[4], vc[1], w2c);
                fma2(acc[5], vc[1], w2a); fma2(acc[5], vc[2], w2b); fma2(acc[5], vc[3], w2c);
                fma2(acc[6], vc[3], w2a); fma2(acc[6], vc[4], w2b); fma2(acc[6], vc[5], w2c);
                fma2(acc[7], vc[5], w2a); fma2(acc[7], vc[6], w2b); fma2(acc[7], vc[7], w2c);
                vtop = vc[7];                           // v15 of this lane
            }

            // halo exchange (whole warp participates; r uniform per warp)
            f32x2 vm1 = __shfl_up_sync(0xffffffffu, vtop, 8);
            if (xq == 0) vm1 = 0ull;

            if (rvalid) {
                // ---- phase 2: lower chunk vd[j] = conv1(16xq+j) ----
                f32x2 vd[8];
                #pragma unroll
                for (int j = 0; j < 8; j++) vd[j] = rb1;
                #pragma unroll
                for (int dy = 0; dy < 3; dy++) {
                    const float *rowp = &pimg[(r + dy) * 64 + pxb];
                    float4 q0 = *(const float4 *)(rowp + 0);
                    float4 q1 = *(const float4 *)(rowp + 4);
                    float2 q2 = *(const float2 *)(rowp + 8);
                    float f[10] = {q0.x,q0.y,q0.z,q0.w, q1.x,q1.y,q1.z,q1.w,
                                   q2.x,q2.y};
                    f32x2 wa = rw1[dy*3+0], wb = rw1[dy*3+1], wc = rw1[dy*3+2];
                    #pragma unroll
                    for (int j = 0; j < 8; j++) {
                        fma2(vd[j], pk2(f[j+0], f[j+0]), wa);
                        fma2(vd[j], pk2(f[j+1], f[j+1]), wb);
                        fma2(vd[j], pk2(f[j+2], f[j+2]), wc);
                    }
                }
                #pragma unroll
                for (int j = 0; j < 8; j++) vd[j] = lky2(vd[j]);
                // conv2 lower outputs: o=0..3, plus o=4's pending v7 term
                fma2(acc[0], vm1,   w2a); fma2(acc[0], vd[0], w2b); fma2(acc[0], vd[1], w2c);
                fma2(acc[1], vd[1], w2a); fma2(acc[1], vd[2], w2b); fma2(acc[1], vd[3], w2c);
                fma2(acc[2], vd[3], w2a); fma2(acc[2], vd[4], w2b); fma2(acc[2], vd[5], w2c);
                fma2(acc[3], vd[5], w2a); fma2(acc[3], vd[6], w2b); fma2(acc[3], vd[7], w2c);
                fma2(acc[4], vd[7], w2a);
            }
        }

        // ---- reduce over 16 channels (f32x2 halves + cp lanes) ----
        #pragma unroll
        for (int o = 0; o < 8; o++) {
            float lo, hi; unpk2(acc[o], lo, hi);
            float s = lo + hi;
            s += __shfl_xor_sync(0xffffffffu, s, 1);
            s += __shfl_xor_sync(0xffffffffu, s, 2);
            s += __shfl_xor_sync(0xffffffffu, s, 4);
            if (cp == 0 && o < n_out)
                emb_s[i2 * 30 + 8 * xq + o] = lky(s + bias2);
        }
    }
    __syncthreads();

    float *eo = emb_out + (size_t)blockIdx.x * EMB;
    for (int i = tid; i < EMB; i += 256) eo[i] = emb_s[i];
}

// =====================================================================
// K-split GEMM: Cy[M x 100] = A[:, kbeg:kend] @ W[kbeg:kend, :] (+bias y==0)
// blockIdx.y selects K-half; output goes to C + y*M*100. No activation.
// CTA tile 64 x 100; 200 active threads, each 8 rows x 4 cols.
// =====================================================================
__global__ void __launch_bounds__(256) gemm100_ks_kernel(
    const float *__restrict__ A, const float *__restrict__ W,
    const float *__restrict__ bias, float *__restrict__ C,
    int M, int K, int chunk)
{
    __shared__ __align__(16) float As[32][65];
    __shared__ __align__(16) float Ws[32][104];

    const int tid = threadIdx.x;
    const int row0 = blockIdx.x * 64;
    const int kbeg = blockIdx.y * chunk;
    const int kend = min(K, kbeg + chunk);
    float *Cout = C + (size_t)blockIdx.y * M * 100;
    const int tx = tid % 25;
    const int ty = tid / 25;
    const bool act = (tid < 200);

    f32x2 acc[8][2];
    #pragma unroll
    for (int r = 0; r < 8; r++) { acc[r][0] = 0ull; acc[r][1] = 0ull; }

    for (int k0 = kbeg; k0 < kend; k0 += 32) {
        for (int e = tid; e < 64 * 32; e += 256) {
            int m = e >> 5, kk = e & 31;
            int k = k0 + kk;
            As[kk][m] = (k < kend) ? A[(size_t)(row0 + m) * K + k] : 0.f;
        }
        for (int e = tid; e < 32 * 100; e += 256) {
            int kk = e / 100, j = e % 100;
            int k = k0 + kk;
            Ws[kk][j] = (k < kend) ? W[(size_t)k * 100 + j] : 0.f;
        }
        __syncthreads();
        if (act) {
            #pragma unroll
            for (int kk = 0; kk < 32; kk++) {
                f32x2 w0 = *(const f32x2 *)&Ws[kk][4 * tx];
                f32x2 w1 = *(const f32x2 *)&Ws[kk][4 * tx + 2];
                #pragma unroll
                for (int r = 0; r < 8; r++) {
                    float a = As[kk][8 * ty + r];
                    f32x2 aa = pk2(a, a);
                    fma2(acc[r][0], aa, w0);
                    fma2(acc[r][1], aa, w1);
                }
            }
        }
        __syncthreads();
    }
    if (act) {
        float b0 = 0.f, b1_ = 0.f, b2_ = 0.f, b3 = 0.f;
        if (blockIdx.y == 0) {
            b0 = bias[4 * tx + 0]; b1_ = bias[4 * tx + 1];
            b2_ = bias[4 * tx + 2]; b3 = bias[4 * tx + 3];
        }
        #pragma unroll
        for (int r = 0; r < 8; r++) {
            float x0, x1, x2, x3;
            unpk2(acc[r][0], x0, x1);
            unpk2(acc[r][1], x2, x3);
            float4 v = make_float4(x0 + b0, x1 + b1_, x2 + b2_, x3 + b3);
            *(float4 *)&Cout[(size_t)(row0 + 8 * ty + r) * 100 + 4 * tx] = v;
        }
    }
}

// =====================================================================
// Recurrence: one CTA per batch element; E = E0 + E1 (K-split halves).
// =====================================================================
__global__ void __launch_bounds__(512) recurrence_kernel(
    const float *__restrict__ Rw, const float *__restrict__ Rb,
    const float *__restrict__ Qw, const float *__restrict__ E0,
    const float *__restrict__ E1, float *__restrict__ Hall)
{
    __shared__ __align__(16) float sH[HSZ];
    __shared__ float sRt[QS];
    __shared__ __align__(16) float part[1008];

    const int tid = threadIdx.x;
    const int b   = blockIdx.x;
    const int jp  = tid % 50;
    const int ks  = tid / 50;
    const bool act = (tid < 500);

    f32x2 w1r[40];
    f32x2 w2r[10];
    if (act) {
        #pragma unroll
        for (int kk = 0; kk < 40; kk++) {
            int k = ks * 40 + kk;
            w1r[kk] = *(const f32x2 *)&Rw[(size_t)k * 100 + 2 * jp];
        }
        #pragma unroll
        for (int kk = 0; kk < 10; kk++) {
            int k = ks * 10 + kk;
            w2r[kk] = *(const f32x2 *)&Qw[(size_t)(750 + k) * 100 + 2 * jp];
        }
    }
    for (int i = tid; i < HSZ; i += 512) sH[i] = 0.f;
    __syncthreads();

    const float *Eb0 = E0 + (size_t)b * TT * QS;
    const float *Eb1 = E1 + (size_t)b * TT * QS;
    float *Hb = Hall + (size_t)b * TT * HSZ;

    for (int t = 0; t < TT; t++) {
        if (act) {
            f32x2 a0 = 0ull, a1 = 0ull;
            #pragma unroll
            for (int kk = 0; kk < 40; kk += 2) {
                float h0 = sH[ks * 40 + kk];
                float h1 = sH[ks * 40 + kk + 1];
                fma2(a0, pk2(h0, h0), w1r[kk]);
                fma2(a1, pk2(h1, h1), w1r[kk + 1]);
            }
            *(f32x2 *)&part[ks * 100 + 2 * jp] = add2(a0, a1);
        }
        __syncthreads();
        if (tid < 100) {
            float s = Rb[tid];
            #pragma unroll
            for (int ss = 0; ss < 10; ss++) s += part[ss * 100 + tid];
            sRt[tid] = tanhf(s);
        }
        __syncthreads();
        if (act) {
            f32x2 a = 0ull;
            #pragma unroll
            for (int kk = 0; kk < 10; kk++) {
                float h = sRt[ks * 10 + kk];
                fma2(a, pk2(h, h), w2r[kk]);
            }
            *(f32x2 *)&part[ks * 100 + 2 * jp] = a;
        }
        __syncthreads();
        if (tid < HSZ) {
            int j = tid % 100;
            float s = Eb0[t * QS + j] + Eb1[t * QS + j];
            #pragma unroll
            for (int ss = 0; ss < 10; ss++) s += part[ss * 100 + j];
            float q = tanhf(s);
            const float alphas[4] = {0.0f, 0.25f, 0.5f, 0.95f};
            float al = alphas[tid / 100];
            float hn = al * sH[tid] + (1.f - al) * q;
            sH[tid] = hn;
            Hb[t * HSZ + tid] = hn;
        }
        __syncthreads();
    }
}

// =====================================================================
// Logits + softmax; consumes tanh(O0 + O1 + bias) on the fly.
// =====================================================================
__global__ void __launch_bounds__(256) logits_kernel(
    const float *__restrict__ O0, const float *__restrict__ O1,
    const float *__restrict__ OutW, const float *__restrict__ OutB,
    float *__restrict__ out)
{
    const int b = blockIdx.x, tid = threadIdx.x;
    const size_t base = (size_t)b * (TT * QS);

    float acc[NCLS];
    #pragma unroll
    for (int c = 0; c < NCLS; c++) acc[c] = 0.f;

    for (int i = tid; i < TT * QS; i += 256) {
        float v = tanhf(O0[base + i] + O1[base + i]);
        const float *wr = OutW + (size_t)i * NCLS;
        #pragma unroll
        for (int c = 0; c < NCLS; c++) acc[c] += v * wr[c];
    }
    #pragma unroll
    for (int c = 0; c < NCLS; c++)
        #pragma unroll
        for (int o = 16; o > 0; o >>= 1)
            acc[c] += __shfl_down_sync(0xffffffffu, acc[c], o);

    __shared__ float wpart[8][NCLS];
    int w = tid >> 5, l = tid & 31;
    if (l == 0)
        #pragma unroll
        for (int c = 0; c < NCLS; c++) wpart[w][c] = acc[c];
    __syncthreads();

    __shared__ float slog[NCLS];
    if (tid < NCLS) {
        float s = OutB[tid];
        #pragma unroll
        for (int ww = 0; ww < 8; ww++) s += wpart[ww][tid];
        slog[tid] = s;
    }
    __syncthreads();
    __shared__ float smax, ssum;
    if (tid == 0) {
        float m = slog[0];
        #pragma unroll
        for (int c = 1; c < NCLS; c++) m = fmaxf(m, slog[c]);
        float su = 0.f;
        #pragma unroll
        for (int c = 0; c < NCLS; c++) su += expf(slog[c] - m);
        smax = m; ssum = su;
    }
    __syncthreads();
    if (tid < NCLS) out[(size_t)b * NCLS + tid] = expf(slog[tid] - smax) / ssum;
}

// =====================================================================
extern "C" void kernel_launch(void *const *d_in, const int *in_sizes, int n_in,
                              void *d_out, int out_size)
{
    const float *In     = (const float *)d_in[0];
    const float *conv1w = (const float *)d_in[1];
    const float *conv1b = (const float *)d_in[2];
    const float *conv2w = (const float *)d_in[3];
    const float *conv2b = (const float *)d_in[4];
    const float *Rw     = (const float *)d_in[5];
    const float *Rb     = (const float *)d_in[6];
    const float *Qw     = (const float *)d_in[7];
    const float *Qb     = (const float *)d_in[8];
    const float *Ow     = (const float *)d_in[9];
    const float *Obias  = (const float *)d_in[10];
    const float *OutW   = (const float *)d_in[11];
    const float *OutB   = (const float *)d_in[12];
    float *out = (float *)d_out;

    float *emb, *E, *Hall, *OutAll;
    cudaGetSymbolAddress((void **)&emb,    g_emb);
    cudaGetSymbolAddress((void **)&E,      g_E);
    cudaGetSymbolAddress((void **)&Hall,   g_Hall);
    cudaGetSymbolAddress((void **)&OutAll, g_OutAll);

    // position-shifters so ncu capture lands on conv
    nop_kernel_a<<<1, 32>>>();
    nop_kernel_b<<<1, 32>>>();
    nop_kernel_c<<<1, 32>>>();

    conv_embed_kernel<<<NIMG, 256>>>(In, conv1w, conv1b, conv2w, conv2b, emb);

    // E halves: K = 750, chunk = 384
    gemm100_ks_kernel<<<dim3(NIMG / 64, 2), 256>>>(emb, Qw, Qb, E, NIMG, EMB, 384);

    recurrence_kernel<<<BB, 512>>>(Rw, Rb, Qw, E, E + (size_t)NIMG * QS, Hall);

    // O halves: K = 400, chunk = 224 ; tanh + Obias applied in logits
    gemm100_ks_kernel<<<dim3(NIMG / 64, 2), 256>>>(Hall, Ow, Obias, OutAll, NIMG, HSZ, 224);

    logits_kernel<<<BB, 256>>>(OutAll, OutAll + (size_t)NIMG * QS, OutW, OutB, out);
}